// round 8
// baseline (speedup 1.0000x reference)
#include <cuda_runtime.h>
#include <math.h>

// ---------------- problem constants ----------------
#define NB      16          // batch
#define LL      512         // lookback == d_model
#define CC      321         // channels == scan length S
#define MROWS   (NB*CC)     // 5136 rows for all GEMMs
#define DMODEL  512
#define DINNER  1024
#define DSTATE  16
#define DTRANK  32
#define HOR     96
#define NBLOCKS 3
#define NSPLIT  8           // split-K factor for skinny GEMMs

// ---------------- scratch (device globals: no allocation allowed) ----------
__device__ float g_h   [MROWS * DMODEL];
__device__ float g_xz  [MROWS * 2 * DINNER];            // x_ = cols [0,1024), z = [1024,2048)
__device__ float g_dbc [MROWS * (DTRANK + 2*DSTATE)];   // delta_raw | Bm | Cm
__device__ float g_dt  [MROWS * DINNER];
__device__ float g_yz  [MROWS * DINNER];
__device__ float g_part[NSPLIT * MROWS * 128];          // split-K partials (21 MB)

// ---------------- epilogues -------------------------------------------------
enum { EPI_NONE = 0, EPI_SOFTPLUS = 1, EPI_GELU = 2 };

__device__ __forceinline__ float apply_epi(int EPI, float v) {
    if (EPI == EPI_SOFTPLUS) return (v > 20.f) ? v : log1pf(__expf(v));
    if (EPI == EPI_GELU)     return 0.5f * v * (1.f + erff(v * 0.70710678118654752f));
    return v;
}

__device__ __forceinline__ unsigned f2tf32(float f) {
    unsigned u;
    asm("cvt.rna.tf32.f32 %0, %1;" : "=r"(u) : "f"(f));
    return u;
}

__device__ __forceinline__ void mma_tf32(float d[4],
                                         unsigned a0, unsigned a1, unsigned a2, unsigned a3,
                                         unsigned b0, unsigned b1) {
    asm volatile(
        "mma.sync.aligned.m16n8k8.row.col.f32.tf32.tf32.f32 "
        "{%0,%1,%2,%3}, {%4,%5,%6,%7}, {%8,%9}, {%0,%1,%2,%3};"
        : "+f"(d[0]), "+f"(d[1]), "+f"(d[2]), "+f"(d[3])
        : "r"(a0), "r"(a1), "r"(a2), "r"(a3), "r"(b0), "r"(b1));
}

// ============================================================================
// Shared TF32 GEMM machinery: BM=BN=128, BK=16, 8 warps (2x4), 64x32 warp tile
// A: [M,K] row-major lda. W: [N,K] row-major contiguous (ldw = full K).
// ============================================================================
struct MmaCtx {
    int lane, warp_m, warp_n, g, t, lm, kg;
};

template<int EPI, bool SPLITK>
__global__ __launch_bounds__(256, 2)
void mma_gemm(const float* __restrict__ A, int lda,
              const float* __restrict__ W, int ldw,
              const float* __restrict__ bias,
              float* __restrict__ C, int ldc,
              int M, int N, int K) {
    constexpr int BM = 128, BK = 16, LDS = 136;
    __shared__ unsigned As[2][BK * LDS];
    __shared__ unsigned Bs[2][BK * LDS];

    const int tid  = threadIdx.x;
    const int lane = tid & 31;
    const int wid  = tid >> 5;
    const int warp_m = wid & 1;
    const int warp_n = wid >> 1;
    const int g = lane >> 2, t = lane & 3;

    const int bM = blockIdx.y * BM;
    const int bN = blockIdx.x * 128;

    const int lm = tid & 127;
    const int kg = tid >> 7;

    // split-K: this CTA covers K range [kbase, kbase + Kloc)
    const int Kloc  = SPLITK ? (K / NSPLIT) : K;
    const int kbase = SPLITK ? blockIdx.z * Kloc : 0;

    float d[4][4][4];
#pragma unroll
    for (int i = 0; i < 4; i++)
#pragma unroll
        for (int j = 0; j < 4; j++)
#pragma unroll
            for (int q = 0; q < 4; q++) d[i][j][q] = 0.f;

    float4 ra0, ra1, rb0, rb1;

    const int mrow = bM + lm;
    const int nrow = bN + lm;
    const float* Abase = A + (size_t)mrow * lda + kbase + kg * 4;
    const float* Wbase = W + (size_t)nrow * ldw + kbase + kg * 4;
    const bool mval = (mrow < M);
    const bool nval = (nrow < N);

    auto ldg = [&](int kt) {
        ra0 = mval ? *(const float4*)(Abase + kt)     : make_float4(0.f,0.f,0.f,0.f);
        ra1 = mval ? *(const float4*)(Abase + kt + 8) : make_float4(0.f,0.f,0.f,0.f);
        rb0 = nval ? *(const float4*)(Wbase + kt)     : make_float4(0.f,0.f,0.f,0.f);
        rb1 = nval ? *(const float4*)(Wbase + kt + 8) : make_float4(0.f,0.f,0.f,0.f);
    };
    auto sts = [&](int buf) {
        unsigned* as = As[buf];
        unsigned* bs = Bs[buf];
        const int k0 = kg * 4, k1 = kg * 4 + 8;
        as[(k0+0)*LDS + lm] = f2tf32(ra0.x);
        as[(k0+1)*LDS + lm] = f2tf32(ra0.y);
        as[(k0+2)*LDS + lm] = f2tf32(ra0.z);
        as[(k0+3)*LDS + lm] = f2tf32(ra0.w);
        as[(k1+0)*LDS + lm] = f2tf32(ra1.x);
        as[(k1+1)*LDS + lm] = f2tf32(ra1.y);
        as[(k1+2)*LDS + lm] = f2tf32(ra1.z);
        as[(k1+3)*LDS + lm] = f2tf32(ra1.w);
        bs[(k0+0)*LDS + lm] = f2tf32(rb0.x);
        bs[(k0+1)*LDS + lm] = f2tf32(rb0.y);
        bs[(k0+2)*LDS + lm] = f2tf32(rb0.z);
        bs[(k0+3)*LDS + lm] = f2tf32(rb0.w);
        bs[(k1+0)*LDS + lm] = f2tf32(rb1.x);
        bs[(k1+1)*LDS + lm] = f2tf32(rb1.y);
        bs[(k1+2)*LDS + lm] = f2tf32(rb1.z);
        bs[(k1+3)*LDS + lm] = f2tf32(rb1.w);
    };

    ldg(0);
    sts(0);
    __syncthreads();

    const int nkt = Kloc / BK;
    for (int it = 0; it < nkt; it++) {
        const int buf = it & 1;
        if (it + 1 < nkt) ldg((it + 1) * BK);

        const unsigned* as = As[buf];
        const unsigned* bs = Bs[buf];
#pragma unroll
        for (int kk = 0; kk < 2; kk++) {
            const int kr = kk * 8;
            unsigned af[4][4], bf[4][2];
#pragma unroll
            for (int i = 0; i < 4; i++) {
                const int mr = warp_m * 64 + i * 16 + g;
                af[i][0] = as[(kr + t    ) * LDS + mr    ];
                af[i][1] = as[(kr + t    ) * LDS + mr + 8];
                af[i][2] = as[(kr + t + 4) * LDS + mr    ];
                af[i][3] = as[(kr + t + 4) * LDS + mr + 8];
            }
#pragma unroll
            for (int j = 0; j < 4; j++) {
                const int nc = warp_n * 32 + j * 8 + g;
                bf[j][0] = bs[(kr + t    ) * LDS + nc];
                bf[j][1] = bs[(kr + t + 4) * LDS + nc];
            }
#pragma unroll
            for (int i = 0; i < 4; i++)
#pragma unroll
                for (int j = 0; j < 4; j++)
                    mma_tf32(d[i][j], af[i][0], af[i][1], af[i][2], af[i][3],
                             bf[j][0], bf[j][1]);
        }

        if (it + 1 < nkt) sts(buf ^ 1);
        __syncthreads();
    }

    // epilogue
    if (SPLITK) {
        // write raw partials to g_part at ((z*MROWS + row) * 128 + col)
        float* P = g_part + (size_t)blockIdx.z * MROWS * 128;
#pragma unroll
        for (int i = 0; i < 4; i++) {
            const int row0 = bM + warp_m * 64 + i * 16 + g;
            const int row1 = row0 + 8;
#pragma unroll
            for (int j = 0; j < 4; j++) {
                const int col = warp_n * 32 + j * 8 + 2 * t;   // local col (0..127)
                if (row0 < M) *(float2*)&P[(size_t)row0 * 128 + col] = make_float2(d[i][j][0], d[i][j][1]);
                if (row1 < M) *(float2*)&P[(size_t)row1 * 128 + col] = make_float2(d[i][j][2], d[i][j][3]);
            }
        }
    } else {
#pragma unroll
        for (int i = 0; i < 4; i++) {
            const int row0 = bM + warp_m * 64 + i * 16 + g;
            const int row1 = row0 + 8;
#pragma unroll
            for (int j = 0; j < 4; j++) {
                const int col = bN + warp_n * 32 + j * 8 + 2 * t;
                if (col >= N) continue;
                const float bs0 = bias[col], bs1 = bias[col + 1];
                if (row0 < M) {
                    float2 v;
                    v.x = apply_epi(EPI, d[i][j][0] + bs0);
                    v.y = apply_epi(EPI, d[i][j][1] + bs1);
                    *(float2*)&C[(size_t)row0 * ldc + col] = v;
                }
                if (row1 < M) {
                    float2 v;
                    v.x = apply_epi(EPI, d[i][j][2] + bs0);
                    v.y = apply_epi(EPI, d[i][j][3] + bs1);
                    *(float2*)&C[(size_t)row1 * ldc + col] = v;
                }
            }
        }
    }
}

// ---------------- split-K reduce: g_dbc = sum_s part + bias ----------------
__global__ void dbc_reduce_kernel(const float* __restrict__ b_xp) {
    int idx = blockIdx.x * blockDim.x + threadIdx.x;
    if (idx >= MROWS * 64) return;
    int m = idx >> 6;
    int n = idx & 63;
    float s = b_xp[n];
#pragma unroll
    for (int z = 0; z < NSPLIT; z++)
        s += g_part[((size_t)z * MROWS + m) * 128 + n];
    g_dbc[(size_t)m * 64 + n] = s;
}

// -------- split-K reduce + transpose + seq_last for the op GEMM ------------
// out[b, hz, c] = sum_s part[s][b*CC + c][hz] + b_op[hz] + x[b, L-1, c]
__global__ void final_reduce_kernel(const float* __restrict__ x,
                                    const float* __restrict__ b_op,
                                    float* __restrict__ out) {
    int idx = blockIdx.x * blockDim.x + threadIdx.x;
    if (idx >= NB * HOR * CC) return;
    int c  = idx % CC;
    int hz = (idx / CC) % HOR;
    int b  = idx / (CC * HOR);
    int m  = b * CC + c;
    float s = b_op[hz];
#pragma unroll
    for (int z = 0; z < NSPLIT; z++)
        s += g_part[((size_t)z * MROWS + m) * 128 + hz];
    float last = x[((size_t)b * LL + (LL - 1)) * CC + c];
    out[idx] = s + last;
}

// ---------------- prep: h[b,c,l] = x[b,l,c] - x[b,L-1,c] -------------------
__global__ void prep_kernel(const float* __restrict__ x) {
    __shared__ float tile[32][33];
    int b  = blockIdx.z;
    int l0 = blockIdx.x * 32;
    int c0 = blockIdx.y * 32;
    int tx = threadIdx.x, ty = threadIdx.y;
    const float* xb = x + (size_t)b * LL * CC;
#pragma unroll
    for (int j = 0; j < 32; j += 8) {
        int l = l0 + ty + j, c = c0 + tx;
        tile[ty + j][tx] = (c < CC) ? xb[l * CC + c] : 0.f;
    }
    __syncthreads();
#pragma unroll
    for (int j = 0; j < 32; j += 8) {
        int c = c0 + ty + j, l = l0 + tx;
        if (c < CC) {
            float last = xb[(LL - 1) * CC + c];
            g_h[((size_t)b * CC + c) * DMODEL + l] = tile[tx][ty + j] - last;
        }
    }
}

// ---------------- selective scan + y, fused -------------------------------
// 8 threads per (b,d) lane, 2 states each (131K threads for latency hiding).
__global__ __launch_bounds__(256)
void scan_kernel(const float* __restrict__ A_log, const float* __restrict__ Dp) {
    const int sub = threadIdx.x & 7;                 // state group (2 states)
    const int d   = blockIdx.x * 32 + (threadIdx.x >> 3);
    const int b   = blockIdx.y;

    const float a0 = -__expf(A_log[d * DSTATE + sub * 2 + 0]);
    const float a1 = -__expf(A_log[d * DSTATE + sub * 2 + 1]);
    const float dp = Dp[d];

    float h0 = 0.f, h1 = 0.f;

    const float* xz_b  = g_xz  + (size_t)b * CC * 2 * DINNER;
    const float* dt_b  = g_dt  + (size_t)b * CC * DINNER;
    const float* dbc_b = g_dbc + (size_t)b * CC * (DTRANK + 2 * DSTATE);
    float*       yz_b  = g_yz  + (size_t)b * CC * DINNER;

    for (int t = 0; t < CC; t++) {
        const float delta = dt_b[t * DINNER + d];
        const float xv    = xz_b[t * 2 * DINNER + d];
        const float zv    = xz_b[t * 2 * DINNER + DINNER + d];
        const float2 Bm = *reinterpret_cast<const float2*>(dbc_b + t * 64 + DTRANK + sub * 2);
        const float2 Cm = *reinterpret_cast<const float2*>(dbc_b + t * 64 + DTRANK + DSTATE + sub * 2);

        const float dx = delta * xv;
        h0 = __expf(delta * a0) * h0 + dx * Bm.x;
        h1 = __expf(delta * a1) * h1 + dx * Bm.y;

        float acc = h0 * Cm.x + h1 * Cm.y;
        acc += __shfl_xor_sync(0xffffffffu, acc, 1);
        acc += __shfl_xor_sync(0xffffffffu, acc, 2);
        acc += __shfl_xor_sync(0xffffffffu, acc, 4);

        if (sub == 0) {
            yz_b[t * DINNER + d] = (acc + dp * xv) * zv;
        }
    }
}

// ---------------- launch ----------------------------------------------------
extern "C" void kernel_launch(void* const* d_in, const int* in_sizes, int n_in,
                              void* d_out, int out_size) {
    const float* x     = (const float*)d_in[0];
    const float* W_in  = (const float*)d_in[1];
    const float* b_in  = (const float*)d_in[2];
    const float* W_xp  = (const float*)d_in[3];
    const float* b_xp  = (const float*)d_in[4];
    const float* W_dt  = (const float*)d_in[5];
    const float* b_dt  = (const float*)d_in[6];
    const float* A_log = (const float*)d_in[7];
    const float* Dp    = (const float*)d_in[8];
    const float* W_out = (const float*)d_in[9];
    const float* b_out = (const float*)d_in[10];
    const float* W_op  = (const float*)d_in[11];
    const float* b_op  = (const float*)d_in[12];
    float* out = (float*)d_out;

    float *h, *xz, *dbc, *dt, *yz;
    cudaGetSymbolAddress((void**)&h,   g_h);
    cudaGetSymbolAddress((void**)&xz,  g_xz);
    cudaGetSymbolAddress((void**)&dbc, g_dbc);
    cudaGetSymbolAddress((void**)&dt,  g_dt);
    cudaGetSymbolAddress((void**)&yz,  g_yz);

    prep_kernel<<<dim3(LL / 32, (CC + 31) / 32, NB), dim3(32, 8)>>>(x);

    const int M  = MROWS;                 // 5136
    const int gM = (M + 127) / 128;       // 41

    for (int blk = 0; blk < NBLOCKS; blk++) {
        // xz = h @ W_in^T + b_in            [M, 2048], K=512   (TF32)
        mma_gemm<EPI_NONE, false><<<dim3(2 * DINNER / 128, gM), 256>>>(
            h, DMODEL, W_in, DMODEL, b_in, xz, 2 * DINNER, M, 2 * DINNER, DMODEL);

        // dbc partials: x_ @ W_xp^T         [M, 64], K=1024    (TF32 split-K 8)
        mma_gemm<EPI_NONE, true><<<dim3(1, gM, NSPLIT), 256>>>(
            xz, 2 * DINNER, W_xp, DINNER, nullptr, nullptr, 0, M, 64, DINNER);
        dbc_reduce_kernel<<<(MROWS * 64 + 255) / 256, 256>>>(b_xp);

        // dt = softplus(dbc[:, :32] @ W_dt^T + b_dt)  [M, 1024], K=32  (TF32)
        mma_gemm<EPI_SOFTPLUS, false><<<dim3(DINNER / 128, gM), 256>>>(
            dbc, 64, W_dt, DTRANK, b_dt, dt, DINNER, M, DINNER, DTRANK);

        // selective scan + y*z
        scan_kernel<<<dim3(DINNER / 32, NB), 256>>>(A_log, Dp);

        // h = gelu(yz @ W_out^T + b_out)    [M, 512], K=1024   (TF32)
        mma_gemm<EPI_GELU, false><<<dim3(DMODEL / 128, gM), 256>>>(
            yz, DINNER, W_out, DINNER, b_out, h, DMODEL, M, DMODEL, DINNER);
    }

    // op partials: h @ W_op^T               [M, 96], K=512     (TF32 split-K 8)
    mma_gemm<EPI_NONE, true><<<dim3(1, gM, NSPLIT), 256>>>(
        h, DMODEL, W_op, DMODEL, nullptr, nullptr, 0, M, HOR, DMODEL);

    // out = reduce(partials) + b_op, transposed, + seq_last
    final_reduce_kernel<<<(NB * HOR * CC + 255) / 256, 256>>>(x, b_op, out);
}

// round 9
// speedup vs baseline: 1.0004x; 1.0004x over previous
#include <cuda_runtime.h>
#include <math.h>

// ---------------- problem constants ----------------
#define NB      16          // batch
#define LL      512         // lookback == d_model
#define CC      321         // channels == scan length S
#define MROWS   (NB*CC)     // 5136 rows for all GEMMs
#define DMODEL  512
#define DINNER  1024
#define DSTATE  16
#define DTRANK  32
#define HOR     96
#define NBLOCKS 3
#define NSPLIT  8           // split-K factor for skinny GEMMs

// ---------------- scratch (device globals: no allocation allowed) ----------
__device__ float g_h   [MROWS * DMODEL];
__device__ float g_xz  [MROWS * 2 * DINNER];            // x_ = cols [0,1024), z = [1024,2048)
__device__ float g_dbc [MROWS * (DTRANK + 2*DSTATE)];   // delta_raw | Bm | Cm
__device__ float g_dt  [MROWS * DINNER];
__device__ float g_yz  [MROWS * DINNER];
__device__ float g_part[NSPLIT * MROWS * 128];          // split-K partials (21 MB)

// ---------------- epilogues -------------------------------------------------
enum { EPI_NONE = 0, EPI_SOFTPLUS = 1, EPI_GELU = 2 };

__device__ __forceinline__ float apply_epi(int EPI, float v) {
    if (EPI == EPI_SOFTPLUS) return (v > 20.f) ? v : log1pf(__expf(v));
    if (EPI == EPI_GELU)     return 0.5f * v * (1.f + erff(v * 0.70710678118654752f));
    return v;
}

__device__ __forceinline__ unsigned f2tf32(float f) {
    unsigned u;
    asm("cvt.rna.tf32.f32 %0, %1;" : "=r"(u) : "f"(f));
    return u;
}

__device__ __forceinline__ void mma_tf32(float d[4],
                                         unsigned a0, unsigned a1, unsigned a2, unsigned a3,
                                         unsigned b0, unsigned b1) {
    asm volatile(
        "mma.sync.aligned.m16n8k8.row.col.f32.tf32.tf32.f32 "
        "{%0,%1,%2,%3}, {%4,%5,%6,%7}, {%8,%9}, {%0,%1,%2,%3};"
        : "+f"(d[0]), "+f"(d[1]), "+f"(d[2]), "+f"(d[3])
        : "r"(a0), "r"(a1), "r"(a2), "r"(a3), "r"(b0), "r"(b1));
}

// ============================================================================
// Shared TF32 GEMM machinery: BM=BN=128, BK=16, 8 warps (2x4), 64x32 warp tile
// A: [M,K] row-major lda. W: [N,K] row-major contiguous (ldw = full K).
// ============================================================================
struct MmaCtx {
    int lane, warp_m, warp_n, g, t, lm, kg;
};

template<int EPI, bool SPLITK>
__global__ __launch_bounds__(256, 2)
void mma_gemm(const float* __restrict__ A, int lda,
              const float* __restrict__ W, int ldw,
              const float* __restrict__ bias,
              float* __restrict__ C, int ldc,
              int M, int N, int K) {
    constexpr int BM = 128, BK = 16, LDS = 136;
    __shared__ unsigned As[2][BK * LDS];
    __shared__ unsigned Bs[2][BK * LDS];

    const int tid  = threadIdx.x;
    const int lane = tid & 31;
    const int wid  = tid >> 5;
    const int warp_m = wid & 1;
    const int warp_n = wid >> 1;
    const int g = lane >> 2, t = lane & 3;

    const int bM = blockIdx.y * BM;
    const int bN = blockIdx.x * 128;

    const int lm = tid & 127;
    const int kg = tid >> 7;

    // split-K: this CTA covers K range [kbase, kbase + Kloc)
    const int Kloc  = SPLITK ? (K / NSPLIT) : K;
    const int kbase = SPLITK ? blockIdx.z * Kloc : 0;

    float d[4][4][4];
#pragma unroll
    for (int i = 0; i < 4; i++)
#pragma unroll
        for (int j = 0; j < 4; j++)
#pragma unroll
            for (int q = 0; q < 4; q++) d[i][j][q] = 0.f;

    float4 ra0, ra1, rb0, rb1;

    const int mrow = bM + lm;
    const int nrow = bN + lm;
    const float* Abase = A + (size_t)mrow * lda + kbase + kg * 4;
    const float* Wbase = W + (size_t)nrow * ldw + kbase + kg * 4;
    const bool mval = (mrow < M);
    const bool nval = (nrow < N);

    auto ldg = [&](int kt) {
        ra0 = mval ? *(const float4*)(Abase + kt)     : make_float4(0.f,0.f,0.f,0.f);
        ra1 = mval ? *(const float4*)(Abase + kt + 8) : make_float4(0.f,0.f,0.f,0.f);
        rb0 = nval ? *(const float4*)(Wbase + kt)     : make_float4(0.f,0.f,0.f,0.f);
        rb1 = nval ? *(const float4*)(Wbase + kt + 8) : make_float4(0.f,0.f,0.f,0.f);
    };
    auto sts = [&](int buf) {
        unsigned* as = As[buf];
        unsigned* bs = Bs[buf];
        const int k0 = kg * 4, k1 = kg * 4 + 8;
        as[(k0+0)*LDS + lm] = f2tf32(ra0.x);
        as[(k0+1)*LDS + lm] = f2tf32(ra0.y);
        as[(k0+2)*LDS + lm] = f2tf32(ra0.z);
        as[(k0+3)*LDS + lm] = f2tf32(ra0.w);
        as[(k1+0)*LDS + lm] = f2tf32(ra1.x);
        as[(k1+1)*LDS + lm] = f2tf32(ra1.y);
        as[(k1+2)*LDS + lm] = f2tf32(ra1.z);
        as[(k1+3)*LDS + lm] = f2tf32(ra1.w);
        bs[(k0+0)*LDS + lm] = f2tf32(rb0.x);
        bs[(k0+1)*LDS + lm] = f2tf32(rb0.y);
        bs[(k0+2)*LDS + lm] = f2tf32(rb0.z);
        bs[(k0+3)*LDS + lm] = f2tf32(rb0.w);
        bs[(k1+0)*LDS + lm] = f2tf32(rb1.x);
        bs[(k1+1)*LDS + lm] = f2tf32(rb1.y);
        bs[(k1+2)*LDS + lm] = f2tf32(rb1.z);
        bs[(k1+3)*LDS + lm] = f2tf32(rb1.w);
    };

    ldg(0);
    sts(0);
    __syncthreads();

    const int nkt = Kloc / BK;
    for (int it = 0; it < nkt; it++) {
        const int buf = it & 1;
        if (it + 1 < nkt) ldg((it + 1) * BK);

        const unsigned* as = As[buf];
        const unsigned* bs = Bs[buf];
#pragma unroll
        for (int kk = 0; kk < 2; kk++) {
            const int kr = kk * 8;
            unsigned af[4][4], bf[4][2];
#pragma unroll
            for (int i = 0; i < 4; i++) {
                const int mr = warp_m * 64 + i * 16 + g;
                af[i][0] = as[(kr + t    ) * LDS + mr    ];
                af[i][1] = as[(kr + t    ) * LDS + mr + 8];
                af[i][2] = as[(kr + t + 4) * LDS + mr    ];
                af[i][3] = as[(kr + t + 4) * LDS + mr + 8];
            }
#pragma unroll
            for (int j = 0; j < 4; j++) {
                const int nc = warp_n * 32 + j * 8 + g;
                bf[j][0] = bs[(kr + t    ) * LDS + nc];
                bf[j][1] = bs[(kr + t + 4) * LDS + nc];
            }
#pragma unroll
            for (int i = 0; i < 4; i++)
#pragma unroll
                for (int j = 0; j < 4; j++)
                    mma_tf32(d[i][j], af[i][0], af[i][1], af[i][2], af[i][3],
                             bf[j][0], bf[j][1]);
        }

        if (it + 1 < nkt) sts(buf ^ 1);
        __syncthreads();
    }

    // epilogue
    if (SPLITK) {
        // write raw partials to g_part at ((z*MROWS + row) * 128 + col)
        float* P = g_part + (size_t)blockIdx.z * MROWS * 128;
#pragma unroll
        for (int i = 0; i < 4; i++) {
            const int row0 = bM + warp_m * 64 + i * 16 + g;
            const int row1 = row0 + 8;
#pragma unroll
            for (int j = 0; j < 4; j++) {
                const int col = warp_n * 32 + j * 8 + 2 * t;   // local col (0..127)
                if (row0 < M) *(float2*)&P[(size_t)row0 * 128 + col] = make_float2(d[i][j][0], d[i][j][1]);
                if (row1 < M) *(float2*)&P[(size_t)row1 * 128 + col] = make_float2(d[i][j][2], d[i][j][3]);
            }
        }
    } else {
#pragma unroll
        for (int i = 0; i < 4; i++) {
            const int row0 = bM + warp_m * 64 + i * 16 + g;
            const int row1 = row0 + 8;
#pragma unroll
            for (int j = 0; j < 4; j++) {
                const int col = bN + warp_n * 32 + j * 8 + 2 * t;
                if (col >= N) continue;
                const float bs0 = bias[col], bs1 = bias[col + 1];
                if (row0 < M) {
                    float2 v;
                    v.x = apply_epi(EPI, d[i][j][0] + bs0);
                    v.y = apply_epi(EPI, d[i][j][1] + bs1);
                    *(float2*)&C[(size_t)row0 * ldc + col] = v;
                }
                if (row1 < M) {
                    float2 v;
                    v.x = apply_epi(EPI, d[i][j][2] + bs0);
                    v.y = apply_epi(EPI, d[i][j][3] + bs1);
                    *(float2*)&C[(size_t)row1 * ldc + col] = v;
                }
            }
        }
    }
}

// ---------------- split-K reduce: g_dbc = sum_s part + bias ----------------
__global__ void dbc_reduce_kernel(const float* __restrict__ b_xp) {
    int idx = blockIdx.x * blockDim.x + threadIdx.x;
    if (idx >= MROWS * 64) return;
    int m = idx >> 6;
    int n = idx & 63;
    float s = b_xp[n];
#pragma unroll
    for (int z = 0; z < NSPLIT; z++)
        s += g_part[((size_t)z * MROWS + m) * 128 + n];
    g_dbc[(size_t)m * 64 + n] = s;
}

// -------- split-K reduce + transpose + seq_last for the op GEMM ------------
// out[b, hz, c] = sum_s part[s][b*CC + c][hz] + b_op[hz] + x[b, L-1, c]
__global__ void final_reduce_kernel(const float* __restrict__ x,
                                    const float* __restrict__ b_op,
                                    float* __restrict__ out) {
    int idx = blockIdx.x * blockDim.x + threadIdx.x;
    if (idx >= NB * HOR * CC) return;
    int c  = idx % CC;
    int hz = (idx / CC) % HOR;
    int b  = idx / (CC * HOR);
    int m  = b * CC + c;
    float s = b_op[hz];
#pragma unroll
    for (int z = 0; z < NSPLIT; z++)
        s += g_part[((size_t)z * MROWS + m) * 128 + hz];
    float last = x[((size_t)b * LL + (LL - 1)) * CC + c];
    out[idx] = s + last;
}

// ---------------- prep: h[b,c,l] = x[b,l,c] - x[b,L-1,c] -------------------
__global__ void prep_kernel(const float* __restrict__ x) {
    __shared__ float tile[32][33];
    int b  = blockIdx.z;
    int l0 = blockIdx.x * 32;
    int c0 = blockIdx.y * 32;
    int tx = threadIdx.x, ty = threadIdx.y;
    const float* xb = x + (size_t)b * LL * CC;
#pragma unroll
    for (int j = 0; j < 32; j += 8) {
        int l = l0 + ty + j, c = c0 + tx;
        tile[ty + j][tx] = (c < CC) ? xb[l * CC + c] : 0.f;
    }
    __syncthreads();
#pragma unroll
    for (int j = 0; j < 32; j += 8) {
        int c = c0 + ty + j, l = l0 + tx;
        if (c < CC) {
            float last = xb[(LL - 1) * CC + c];
            g_h[((size_t)b * CC + c) * DMODEL + l] = tile[tx][ty + j] - last;
        }
    }
}

// ---------------- selective scan + y, fused -------------------------------
// 8 threads per (b,d) lane, 2 states each (131K threads for latency hiding).
__global__ __launch_bounds__(256)
void scan_kernel(const float* __restrict__ A_log, const float* __restrict__ Dp) {
    const int sub = threadIdx.x & 7;                 // state group (2 states)
    const int d   = blockIdx.x * 32 + (threadIdx.x >> 3);
    const int b   = blockIdx.y;

    const float a0 = -__expf(A_log[d * DSTATE + sub * 2 + 0]);
    const float a1 = -__expf(A_log[d * DSTATE + sub * 2 + 1]);
    const float dp = Dp[d];

    float h0 = 0.f, h1 = 0.f;

    const float* xz_b  = g_xz  + (size_t)b * CC * 2 * DINNER;
    const float* dt_b  = g_dt  + (size_t)b * CC * DINNER;
    const float* dbc_b = g_dbc + (size_t)b * CC * (DTRANK + 2 * DSTATE);
    float*       yz_b  = g_yz  + (size_t)b * CC * DINNER;

    for (int t = 0; t < CC; t++) {
        const float delta = dt_b[t * DINNER + d];
        const float xv    = xz_b[t * 2 * DINNER + d];
        const float zv    = xz_b[t * 2 * DINNER + DINNER + d];
        const float2 Bm = *reinterpret_cast<const float2*>(dbc_b + t * 64 + DTRANK + sub * 2);
        const float2 Cm = *reinterpret_cast<const float2*>(dbc_b + t * 64 + DTRANK + DSTATE + sub * 2);

        const float dx = delta * xv;
        h0 = __expf(delta * a0) * h0 + dx * Bm.x;
        h1 = __expf(delta * a1) * h1 + dx * Bm.y;

        float acc = h0 * Cm.x + h1 * Cm.y;
        acc += __shfl_xor_sync(0xffffffffu, acc, 1);
        acc += __shfl_xor_sync(0xffffffffu, acc, 2);
        acc += __shfl_xor_sync(0xffffffffu, acc, 4);

        if (sub == 0) {
            yz_b[t * DINNER + d] = (acc + dp * xv) * zv;
        }
    }
}

// ---------------- launch ----------------------------------------------------
extern "C" void kernel_launch(void* const* d_in, const int* in_sizes, int n_in,
                              void* d_out, int out_size) {
    const float* x     = (const float*)d_in[0];
    const float* W_in  = (const float*)d_in[1];
    const float* b_in  = (const float*)d_in[2];
    const float* W_xp  = (const float*)d_in[3];
    const float* b_xp  = (const float*)d_in[4];
    const float* W_dt  = (const float*)d_in[5];
    const float* b_dt  = (const float*)d_in[6];
    const float* A_log = (const float*)d_in[7];
    const float* Dp    = (const float*)d_in[8];
    const float* W_out = (const float*)d_in[9];
    const float* b_out = (const float*)d_in[10];
    const float* W_op  = (const float*)d_in[11];
    const float* b_op  = (const float*)d_in[12];
    float* out = (float*)d_out;

    float *h, *xz, *dbc, *dt, *yz;
    cudaGetSymbolAddress((void**)&h,   g_h);
    cudaGetSymbolAddress((void**)&xz,  g_xz);
    cudaGetSymbolAddress((void**)&dbc, g_dbc);
    cudaGetSymbolAddress((void**)&dt,  g_dt);
    cudaGetSymbolAddress((void**)&yz,  g_yz);

    prep_kernel<<<dim3(LL / 32, (CC + 31) / 32, NB), dim3(32, 8)>>>(x);

    const int M  = MROWS;                 // 5136
    const int gM = (M + 127) / 128;       // 41

    for (int blk = 0; blk < NBLOCKS; blk++) {
        // xz = h @ W_in^T + b_in            [M, 2048], K=512   (TF32)
        mma_gemm<EPI_NONE, false><<<dim3(2 * DINNER / 128, gM), 256>>>(
            h, DMODEL, W_in, DMODEL, b_in, xz, 2 * DINNER, M, 2 * DINNER, DMODEL);

        // dbc partials: x_ @ W_xp^T         [M, 64], K=1024    (TF32 split-K 8)
        mma_gemm<EPI_NONE, true><<<dim3(1, gM, NSPLIT), 256>>>(
            xz, 2 * DINNER, W_xp, DINNER, nullptr, nullptr, 0, M, 64, DINNER);
        dbc_reduce_kernel<<<(MROWS * 64 + 255) / 256, 256>>>(b_xp);

        // dt = softplus(dbc[:, :32] @ W_dt^T + b_dt)  [M, 1024], K=32  (TF32)
        mma_gemm<EPI_SOFTPLUS, false><<<dim3(DINNER / 128, gM), 256>>>(
            dbc, 64, W_dt, DTRANK, b_dt, dt, DINNER, M, DINNER, DTRANK);

        // selective scan + y*z
        scan_kernel<<<dim3(DINNER / 32, NB), 256>>>(A_log, Dp);

        // h = gelu(yz @ W_out^T + b_out)    [M, 512], K=1024   (TF32)
        mma_gemm<EPI_GELU, false><<<dim3(DMODEL / 128, gM), 256>>>(
            yz, DINNER, W_out, DINNER, b_out, h, DMODEL, M, DMODEL, DINNER);
    }

    // op partials: h @ W_op^T               [M, 96], K=512     (TF32 split-K 8)
    mma_gemm<EPI_NONE, true><<<dim3(1, gM, NSPLIT), 256>>>(
        h, DMODEL, W_op, DMODEL, nullptr, nullptr, 0, M, HOR, DMODEL);

    // out = reduce(partials) + b_op, transposed, + seq_last
    final_reduce_kernel<<<(NB * HOR * CC + 255) / 256, 256>>>(x, b_op, out);
}

// round 10
// speedup vs baseline: 1.0080x; 1.0076x over previous
#include <cuda_runtime.h>
#include <math.h>

// ---------------- problem constants ----------------
#define NB      16          // batch
#define LL      512         // lookback == d_model
#define CC      321         // channels == scan length S
#define MROWS   (NB*CC)     // 5136 rows for all GEMMs
#define DMODEL  512
#define DINNER  1024
#define DSTATE  16
#define DTRANK  32
#define HOR     96
#define NBLOCKS 3
#define NSPLIT  8           // split-K factor for skinny GEMMs

// ---------------- scratch (device globals: no allocation allowed) ----------
__device__ float g_h   [MROWS * DMODEL];
__device__ float g_xz  [MROWS * 2 * DINNER];            // x_ = cols [0,1024), z = [1024,2048)
__device__ float g_dbc [MROWS * (DTRANK + 2*DSTATE)];   // delta_raw | Bm | Cm
__device__ float g_dt  [MROWS * DINNER];
__device__ float g_yz  [MROWS * DINNER];
__device__ float g_part[NSPLIT * MROWS * 128];          // split-K partials (21 MB)

// ---------------- epilogues -------------------------------------------------
enum { EPI_NONE = 0, EPI_SOFTPLUS = 1, EPI_GELU = 2 };

__device__ __forceinline__ float apply_epi(int EPI, float v) {
    if (EPI == EPI_SOFTPLUS) return (v > 20.f) ? v : log1pf(__expf(v));
    if (EPI == EPI_GELU)     return 0.5f * v * (1.f + erff(v * 0.70710678118654752f));
    return v;
}

__device__ __forceinline__ unsigned f2tf32(float f) {
    unsigned u;
    asm("cvt.rna.tf32.f32 %0, %1;" : "=r"(u) : "f"(f));
    return u;
}

__device__ __forceinline__ void mma_tf32(float d[4],
                                         unsigned a0, unsigned a1, unsigned a2, unsigned a3,
                                         unsigned b0, unsigned b1) {
    asm volatile(
        "mma.sync.aligned.m16n8k8.row.col.f32.tf32.tf32.f32 "
        "{%0,%1,%2,%3}, {%4,%5,%6,%7}, {%8,%9}, {%0,%1,%2,%3};"
        : "+f"(d[0]), "+f"(d[1]), "+f"(d[2]), "+f"(d[3])
        : "r"(a0), "r"(a1), "r"(a2), "r"(a3), "r"(b0), "r"(b1));
}

// ============================================================================
// Shared TF32 GEMM machinery: BM=BN=128, BK=16, 8 warps (2x4), 64x32 warp tile
// A: [M,K] row-major lda. W: [N,K] row-major contiguous (ldw = full K).
// ============================================================================
struct MmaCtx {
    int lane, warp_m, warp_n, g, t, lm, kg;
};

template<int EPI, bool SPLITK>
__global__ __launch_bounds__(256, 2)
void mma_gemm(const float* __restrict__ A, int lda,
              const float* __restrict__ W, int ldw,
              const float* __restrict__ bias,
              float* __restrict__ C, int ldc,
              int M, int N, int K) {
    constexpr int BM = 128, BK = 16, LDS = 136;
    __shared__ unsigned As[2][BK * LDS];
    __shared__ unsigned Bs[2][BK * LDS];

    const int tid  = threadIdx.x;
    const int lane = tid & 31;
    const int wid  = tid >> 5;
    const int warp_m = wid & 1;
    const int warp_n = wid >> 1;
    const int g = lane >> 2, t = lane & 3;

    const int bM = blockIdx.y * BM;
    const int bN = blockIdx.x * 128;

    const int lm = tid & 127;
    const int kg = tid >> 7;

    // split-K: this CTA covers K range [kbase, kbase + Kloc)
    const int Kloc  = SPLITK ? (K / NSPLIT) : K;
    const int kbase = SPLITK ? blockIdx.z * Kloc : 0;

    float d[4][4][4];
#pragma unroll
    for (int i = 0; i < 4; i++)
#pragma unroll
        for (int j = 0; j < 4; j++)
#pragma unroll
            for (int q = 0; q < 4; q++) d[i][j][q] = 0.f;

    float4 ra0, ra1, rb0, rb1;

    const int mrow = bM + lm;
    const int nrow = bN + lm;
    const float* Abase = A + (size_t)mrow * lda + kbase + kg * 4;
    const float* Wbase = W + (size_t)nrow * ldw + kbase + kg * 4;
    const bool mval = (mrow < M);
    const bool nval = (nrow < N);

    auto ldg = [&](int kt) {
        ra0 = mval ? *(const float4*)(Abase + kt)     : make_float4(0.f,0.f,0.f,0.f);
        ra1 = mval ? *(const float4*)(Abase + kt + 8) : make_float4(0.f,0.f,0.f,0.f);
        rb0 = nval ? *(const float4*)(Wbase + kt)     : make_float4(0.f,0.f,0.f,0.f);
        rb1 = nval ? *(const float4*)(Wbase + kt + 8) : make_float4(0.f,0.f,0.f,0.f);
    };
    auto sts = [&](int buf) {
        unsigned* as = As[buf];
        unsigned* bs = Bs[buf];
        const int k0 = kg * 4, k1 = kg * 4 + 8;
        as[(k0+0)*LDS + lm] = f2tf32(ra0.x);
        as[(k0+1)*LDS + lm] = f2tf32(ra0.y);
        as[(k0+2)*LDS + lm] = f2tf32(ra0.z);
        as[(k0+3)*LDS + lm] = f2tf32(ra0.w);
        as[(k1+0)*LDS + lm] = f2tf32(ra1.x);
        as[(k1+1)*LDS + lm] = f2tf32(ra1.y);
        as[(k1+2)*LDS + lm] = f2tf32(ra1.z);
        as[(k1+3)*LDS + lm] = f2tf32(ra1.w);
        bs[(k0+0)*LDS + lm] = f2tf32(rb0.x);
        bs[(k0+1)*LDS + lm] = f2tf32(rb0.y);
        bs[(k0+2)*LDS + lm] = f2tf32(rb0.z);
        bs[(k0+3)*LDS + lm] = f2tf32(rb0.w);
        bs[(k1+0)*LDS + lm] = f2tf32(rb1.x);
        bs[(k1+1)*LDS + lm] = f2tf32(rb1.y);
        bs[(k1+2)*LDS + lm] = f2tf32(rb1.z);
        bs[(k1+3)*LDS + lm] = f2tf32(rb1.w);
    };

    ldg(0);
    sts(0);
    __syncthreads();

    const int nkt = Kloc / BK;
    for (int it = 0; it < nkt; it++) {
        const int buf = it & 1;
        if (it + 1 < nkt) ldg((it + 1) * BK);

        const unsigned* as = As[buf];
        const unsigned* bs = Bs[buf];
#pragma unroll
        for (int kk = 0; kk < 2; kk++) {
            const int kr = kk * 8;
            unsigned af[4][4], bf[4][2];
#pragma unroll
            for (int i = 0; i < 4; i++) {
                const int mr = warp_m * 64 + i * 16 + g;
                af[i][0] = as[(kr + t    ) * LDS + mr    ];
                af[i][1] = as[(kr + t    ) * LDS + mr + 8];
                af[i][2] = as[(kr + t + 4) * LDS + mr    ];
                af[i][3] = as[(kr + t + 4) * LDS + mr + 8];
            }
#pragma unroll
            for (int j = 0; j < 4; j++) {
                const int nc = warp_n * 32 + j * 8 + g;
                bf[j][0] = bs[(kr + t    ) * LDS + nc];
                bf[j][1] = bs[(kr + t + 4) * LDS + nc];
            }
#pragma unroll
            for (int i = 0; i < 4; i++)
#pragma unroll
                for (int j = 0; j < 4; j++)
                    mma_tf32(d[i][j], af[i][0], af[i][1], af[i][2], af[i][3],
                             bf[j][0], bf[j][1]);
        }

        if (it + 1 < nkt) sts(buf ^ 1);
        __syncthreads();
    }

    // epilogue
    if (SPLITK) {
        // write raw partials to g_part at ((z*MROWS + row) * 128 + col)
        float* P = g_part + (size_t)blockIdx.z * MROWS * 128;
#pragma unroll
        for (int i = 0; i < 4; i++) {
            const int row0 = bM + warp_m * 64 + i * 16 + g;
            const int row1 = row0 + 8;
#pragma unroll
            for (int j = 0; j < 4; j++) {
                const int col = warp_n * 32 + j * 8 + 2 * t;   // local col (0..127)
                if (row0 < M) *(float2*)&P[(size_t)row0 * 128 + col] = make_float2(d[i][j][0], d[i][j][1]);
                if (row1 < M) *(float2*)&P[(size_t)row1 * 128 + col] = make_float2(d[i][j][2], d[i][j][3]);
            }
        }
    } else {
#pragma unroll
        for (int i = 0; i < 4; i++) {
            const int row0 = bM + warp_m * 64 + i * 16 + g;
            const int row1 = row0 + 8;
#pragma unroll
            for (int j = 0; j < 4; j++) {
                const int col = bN + warp_n * 32 + j * 8 + 2 * t;
                if (col >= N) continue;
                const float bs0 = bias[col], bs1 = bias[col + 1];
                if (row0 < M) {
                    float2 v;
                    v.x = apply_epi(EPI, d[i][j][0] + bs0);
                    v.y = apply_epi(EPI, d[i][j][1] + bs1);
                    *(float2*)&C[(size_t)row0 * ldc + col] = v;
                }
                if (row1 < M) {
                    float2 v;
                    v.x = apply_epi(EPI, d[i][j][2] + bs0);
                    v.y = apply_epi(EPI, d[i][j][3] + bs1);
                    *(float2*)&C[(size_t)row1 * ldc + col] = v;
                }
            }
        }
    }
}

// ---------------- split-K reduce: g_dbc = sum_s part + bias ----------------
__global__ void dbc_reduce_kernel(const float* __restrict__ b_xp) {
    int idx = blockIdx.x * blockDim.x + threadIdx.x;
    if (idx >= MROWS * 64) return;
    int m = idx >> 6;
    int n = idx & 63;
    float s = b_xp[n];
#pragma unroll
    for (int z = 0; z < NSPLIT; z++)
        s += g_part[((size_t)z * MROWS + m) * 128 + n];
    g_dbc[(size_t)m * 64 + n] = s;
}

// -------- split-K reduce + transpose + seq_last for the op GEMM ------------
// out[b, hz, c] = sum_s part[s][b*CC + c][hz] + b_op[hz] + x[b, L-1, c]
__global__ void final_reduce_kernel(const float* __restrict__ x,
                                    const float* __restrict__ b_op,
                                    float* __restrict__ out) {
    int idx = blockIdx.x * blockDim.x + threadIdx.x;
    if (idx >= NB * HOR * CC) return;
    int c  = idx % CC;
    int hz = (idx / CC) % HOR;
    int b  = idx / (CC * HOR);
    int m  = b * CC + c;
    float s = b_op[hz];
#pragma unroll
    for (int z = 0; z < NSPLIT; z++)
        s += g_part[((size_t)z * MROWS + m) * 128 + hz];
    float last = x[((size_t)b * LL + (LL - 1)) * CC + c];
    out[idx] = s + last;
}

// ---------------- prep: h[b,c,l] = x[b,l,c] - x[b,L-1,c] -------------------
__global__ void prep_kernel(const float* __restrict__ x) {
    __shared__ float tile[32][33];
    int b  = blockIdx.z;
    int l0 = blockIdx.x * 32;
    int c0 = blockIdx.y * 32;
    int tx = threadIdx.x, ty = threadIdx.y;
    const float* xb = x + (size_t)b * LL * CC;
#pragma unroll
    for (int j = 0; j < 32; j += 8) {
        int l = l0 + ty + j, c = c0 + tx;
        tile[ty + j][tx] = (c < CC) ? xb[l * CC + c] : 0.f;
    }
    __syncthreads();
#pragma unroll
    for (int j = 0; j < 32; j += 8) {
        int c = c0 + ty + j, l = l0 + tx;
        if (c < CC) {
            float last = xb[(LL - 1) * CC + c];
            g_h[((size_t)b * CC + c) * DMODEL + l] = tile[tx][ty + j] - last;
        }
    }
}

// ---------------- selective scan + y, fused -------------------------------
// 8 threads per (b,d) lane, 2 states each (131K threads for latency hiding).
__global__ __launch_bounds__(256)
void scan_kernel(const float* __restrict__ A_log, const float* __restrict__ Dp) {
    const int sub = threadIdx.x & 7;                 // state group (2 states)
    const int d   = blockIdx.x * 32 + (threadIdx.x >> 3);
    const int b   = blockIdx.y;

    const float a0 = -__expf(A_log[d * DSTATE + sub * 2 + 0]);
    const float a1 = -__expf(A_log[d * DSTATE + sub * 2 + 1]);
    const float dp = Dp[d];

    float h0 = 0.f, h1 = 0.f;

    const float* xz_b  = g_xz  + (size_t)b * CC * 2 * DINNER;
    const float* dt_b  = g_dt  + (size_t)b * CC * DINNER;
    const float* dbc_b = g_dbc + (size_t)b * CC * (DTRANK + 2 * DSTATE);
    float*       yz_b  = g_yz  + (size_t)b * CC * DINNER;

    for (int t = 0; t < CC; t++) {
        const float delta = dt_b[t * DINNER + d];
        const float xv    = xz_b[t * 2 * DINNER + d];
        const float zv    = xz_b[t * 2 * DINNER + DINNER + d];
        const float2 Bm = *reinterpret_cast<const float2*>(dbc_b + t * 64 + DTRANK + sub * 2);
        const float2 Cm = *reinterpret_cast<const float2*>(dbc_b + t * 64 + DTRANK + DSTATE + sub * 2);

        const float dx = delta * xv;
        h0 = __expf(delta * a0) * h0 + dx * Bm.x;
        h1 = __expf(delta * a1) * h1 + dx * Bm.y;

        float acc = h0 * Cm.x + h1 * Cm.y;
        acc += __shfl_xor_sync(0xffffffffu, acc, 1);
        acc += __shfl_xor_sync(0xffffffffu, acc, 2);
        acc += __shfl_xor_sync(0xffffffffu, acc, 4);

        if (sub == 0) {
            yz_b[t * DINNER + d] = (acc + dp * xv) * zv;
        }
    }
}

// ---------------- launch ----------------------------------------------------
extern "C" void kernel_launch(void* const* d_in, const int* in_sizes, int n_in,
                              void* d_out, int out_size) {
    const float* x     = (const float*)d_in[0];
    const float* W_in  = (const float*)d_in[1];
    const float* b_in  = (const float*)d_in[2];
    const float* W_xp  = (const float*)d_in[3];
    const float* b_xp  = (const float*)d_in[4];
    const float* W_dt  = (const float*)d_in[5];
    const float* b_dt  = (const float*)d_in[6];
    const float* A_log = (const float*)d_in[7];
    const float* Dp    = (const float*)d_in[8];
    const float* W_out = (const float*)d_in[9];
    const float* b_out = (const float*)d_in[10];
    const float* W_op  = (const float*)d_in[11];
    const float* b_op  = (const float*)d_in[12];
    float* out = (float*)d_out;

    float *h, *xz, *dbc, *dt, *yz;
    cudaGetSymbolAddress((void**)&h,   g_h);
    cudaGetSymbolAddress((void**)&xz,  g_xz);
    cudaGetSymbolAddress((void**)&dbc, g_dbc);
    cudaGetSymbolAddress((void**)&dt,  g_dt);
    cudaGetSymbolAddress((void**)&yz,  g_yz);

    prep_kernel<<<dim3(LL / 32, (CC + 31) / 32, NB), dim3(32, 8)>>>(x);

    const int M  = MROWS;                 // 5136
    const int gM = (M + 127) / 128;       // 41

    for (int blk = 0; blk < NBLOCKS; blk++) {
        // xz = h @ W_in^T + b_in            [M, 2048], K=512   (TF32)
        mma_gemm<EPI_NONE, false><<<dim3(2 * DINNER / 128, gM), 256>>>(
            h, DMODEL, W_in, DMODEL, b_in, xz, 2 * DINNER, M, 2 * DINNER, DMODEL);

        // dbc partials: x_ @ W_xp^T         [M, 64], K=1024    (TF32 split-K 8)
        mma_gemm<EPI_NONE, true><<<dim3(1, gM, NSPLIT), 256>>>(
            xz, 2 * DINNER, W_xp, DINNER, nullptr, nullptr, 0, M, 64, DINNER);
        dbc_reduce_kernel<<<(MROWS * 64 + 255) / 256, 256>>>(b_xp);

        // dt = softplus(dbc[:, :32] @ W_dt^T + b_dt)  [M, 1024], K=32  (TF32)
        mma_gemm<EPI_SOFTPLUS, false><<<dim3(DINNER / 128, gM), 256>>>(
            dbc, 64, W_dt, DTRANK, b_dt, dt, DINNER, M, DINNER, DTRANK);

        // selective scan + y*z
        scan_kernel<<<dim3(DINNER / 32, NB), 256>>>(A_log, Dp);

        // h = gelu(yz @ W_out^T + b_out)    [M, 512], K=1024   (TF32)
        mma_gemm<EPI_GELU, false><<<dim3(DMODEL / 128, gM), 256>>>(
            yz, DINNER, W_out, DINNER, b_out, h, DMODEL, M, DMODEL, DINNER);
    }

    // op partials: h @ W_op^T               [M, 96], K=512     (TF32 split-K 8)
    mma_gemm<EPI_NONE, true><<<dim3(1, gM, NSPLIT), 256>>>(
        h, DMODEL, W_op, DMODEL, nullptr, nullptr, 0, M, HOR, DMODEL);

    // out = reduce(partials) + b_op, transposed, + seq_last
    final_reduce_kernel<<<(NB * HOR * CC + 255) / 256, 256>>>(x, b_op, out);
}

// round 11
// speedup vs baseline: 1.0140x; 1.0059x over previous
#include <cuda_runtime.h>
#include <math.h>

// ---------------- problem constants ----------------
#define NB      16          // batch
#define LL      512         // lookback == d_model
#define CC      321         // channels == scan length S
#define MROWS   (NB*CC)     // 5136 rows for all GEMMs
#define DMODEL  512
#define DINNER  1024
#define DSTATE  16
#define DTRANK  32
#define HOR     96
#define NBLOCKS 3
#define NSPLIT  8           // split-K factor for skinny GEMMs

// ---------------- scratch (device globals: no allocation allowed) ----------
__device__ float g_h   [MROWS * DMODEL];
__device__ float g_xz  [MROWS * 2 * DINNER];            // x_ = cols [0,1024), z = [1024,2048)
__device__ float g_dbc [MROWS * (DTRANK + 2*DSTATE)];   // delta_raw | Bm | Cm
__device__ float g_dt  [MROWS * DINNER];
__device__ float g_yz  [MROWS * DINNER];
__device__ float g_part[NSPLIT * MROWS * 128];          // split-K partials (21 MB)

// ---------------- epilogues -------------------------------------------------
enum { EPI_NONE = 0, EPI_SOFTPLUS = 1, EPI_GELU = 2 };

__device__ __forceinline__ float apply_epi(int EPI, float v) {
    if (EPI == EPI_SOFTPLUS) return (v > 20.f) ? v : log1pf(__expf(v));
    if (EPI == EPI_GELU)     return 0.5f * v * (1.f + erff(v * 0.70710678118654752f));
    return v;
}

__device__ __forceinline__ unsigned f2tf32(float f) {
    unsigned u;
    asm("cvt.rna.tf32.f32 %0, %1;" : "=r"(u) : "f"(f));
    return u;
}

__device__ __forceinline__ void mma_tf32(float d[4],
                                         unsigned a0, unsigned a1, unsigned a2, unsigned a3,
                                         unsigned b0, unsigned b1) {
    asm volatile(
        "mma.sync.aligned.m16n8k8.row.col.f32.tf32.tf32.f32 "
        "{%0,%1,%2,%3}, {%4,%5,%6,%7}, {%8,%9}, {%0,%1,%2,%3};"
        : "+f"(d[0]), "+f"(d[1]), "+f"(d[2]), "+f"(d[3])
        : "r"(a0), "r"(a1), "r"(a2), "r"(a3), "r"(b0), "r"(b1));
}

// ============================================================================
// Shared TF32 GEMM machinery: BM=BN=128, BK=16, 8 warps (2x4), 64x32 warp tile
// A: [M,K] row-major lda. W: [N,K] row-major contiguous (ldw = full K).
// ============================================================================
struct MmaCtx {
    int lane, warp_m, warp_n, g, t, lm, kg;
};

template<int EPI, bool SPLITK>
__global__ __launch_bounds__(256, 2)
void mma_gemm(const float* __restrict__ A, int lda,
              const float* __restrict__ W, int ldw,
              const float* __restrict__ bias,
              float* __restrict__ C, int ldc,
              int M, int N, int K) {
    constexpr int BM = 128, BK = 16, LDS = 136;
    __shared__ unsigned As[2][BK * LDS];
    __shared__ unsigned Bs[2][BK * LDS];

    const int tid  = threadIdx.x;
    const int lane = tid & 31;
    const int wid  = tid >> 5;
    const int warp_m = wid & 1;
    const int warp_n = wid >> 1;
    const int g = lane >> 2, t = lane & 3;

    const int bM = blockIdx.y * BM;
    const int bN = blockIdx.x * 128;

    const int lm = tid & 127;
    const int kg = tid >> 7;

    // split-K: this CTA covers K range [kbase, kbase + Kloc)
    const int Kloc  = SPLITK ? (K / NSPLIT) : K;
    const int kbase = SPLITK ? blockIdx.z * Kloc : 0;

    float d[4][4][4];
#pragma unroll
    for (int i = 0; i < 4; i++)
#pragma unroll
        for (int j = 0; j < 4; j++)
#pragma unroll
            for (int q = 0; q < 4; q++) d[i][j][q] = 0.f;

    float4 ra0, ra1, rb0, rb1;

    const int mrow = bM + lm;
    const int nrow = bN + lm;
    const float* Abase = A + (size_t)mrow * lda + kbase + kg * 4;
    const float* Wbase = W + (size_t)nrow * ldw + kbase + kg * 4;
    const bool mval = (mrow < M);
    const bool nval = (nrow < N);

    auto ldg = [&](int kt) {
        ra0 = mval ? *(const float4*)(Abase + kt)     : make_float4(0.f,0.f,0.f,0.f);
        ra1 = mval ? *(const float4*)(Abase + kt + 8) : make_float4(0.f,0.f,0.f,0.f);
        rb0 = nval ? *(const float4*)(Wbase + kt)     : make_float4(0.f,0.f,0.f,0.f);
        rb1 = nval ? *(const float4*)(Wbase + kt + 8) : make_float4(0.f,0.f,0.f,0.f);
    };
    auto sts = [&](int buf) {
        unsigned* as = As[buf];
        unsigned* bs = Bs[buf];
        const int k0 = kg * 4, k1 = kg * 4 + 8;
        as[(k0+0)*LDS + lm] = f2tf32(ra0.x);
        as[(k0+1)*LDS + lm] = f2tf32(ra0.y);
        as[(k0+2)*LDS + lm] = f2tf32(ra0.z);
        as[(k0+3)*LDS + lm] = f2tf32(ra0.w);
        as[(k1+0)*LDS + lm] = f2tf32(ra1.x);
        as[(k1+1)*LDS + lm] = f2tf32(ra1.y);
        as[(k1+2)*LDS + lm] = f2tf32(ra1.z);
        as[(k1+3)*LDS + lm] = f2tf32(ra1.w);
        bs[(k0+0)*LDS + lm] = f2tf32(rb0.x);
        bs[(k0+1)*LDS + lm] = f2tf32(rb0.y);
        bs[(k0+2)*LDS + lm] = f2tf32(rb0.z);
        bs[(k0+3)*LDS + lm] = f2tf32(rb0.w);
        bs[(k1+0)*LDS + lm] = f2tf32(rb1.x);
        bs[(k1+1)*LDS + lm] = f2tf32(rb1.y);
        bs[(k1+2)*LDS + lm] = f2tf32(rb1.z);
        bs[(k1+3)*LDS + lm] = f2tf32(rb1.w);
    };

    ldg(0);
    sts(0);
    __syncthreads();

    const int nkt = Kloc / BK;
    for (int it = 0; it < nkt; it++) {
        const int buf = it & 1;
        if (it + 1 < nkt) ldg((it + 1) * BK);

        const unsigned* as = As[buf];
        const unsigned* bs = Bs[buf];
#pragma unroll
        for (int kk = 0; kk < 2; kk++) {
            const int kr = kk * 8;
            unsigned af[4][4], bf[4][2];
#pragma unroll
            for (int i = 0; i < 4; i++) {
                const int mr = warp_m * 64 + i * 16 + g;
                af[i][0] = as[(kr + t    ) * LDS + mr    ];
                af[i][1] = as[(kr + t    ) * LDS + mr + 8];
                af[i][2] = as[(kr + t + 4) * LDS + mr    ];
                af[i][3] = as[(kr + t + 4) * LDS + mr + 8];
            }
#pragma unroll
            for (int j = 0; j < 4; j++) {
                const int nc = warp_n * 32 + j * 8 + g;
                bf[j][0] = bs[(kr + t    ) * LDS + nc];
                bf[j][1] = bs[(kr + t + 4) * LDS + nc];
            }
#pragma unroll
            for (int i = 0; i < 4; i++)
#pragma unroll
                for (int j = 0; j < 4; j++)
                    mma_tf32(d[i][j], af[i][0], af[i][1], af[i][2], af[i][3],
                             bf[j][0], bf[j][1]);
        }

        if (it + 1 < nkt) sts(buf ^ 1);
        __syncthreads();
    }

    // epilogue
    if (SPLITK) {
        // write raw partials to g_part at ((z*MROWS + row) * 128 + col)
        float* P = g_part + (size_t)blockIdx.z * MROWS * 128;
#pragma unroll
        for (int i = 0; i < 4; i++) {
            const int row0 = bM + warp_m * 64 + i * 16 + g;
            const int row1 = row0 + 8;
#pragma unroll
            for (int j = 0; j < 4; j++) {
                const int col = warp_n * 32 + j * 8 + 2 * t;   // local col (0..127)
                if (row0 < M) *(float2*)&P[(size_t)row0 * 128 + col] = make_float2(d[i][j][0], d[i][j][1]);
                if (row1 < M) *(float2*)&P[(size_t)row1 * 128 + col] = make_float2(d[i][j][2], d[i][j][3]);
            }
        }
    } else {
#pragma unroll
        for (int i = 0; i < 4; i++) {
            const int row0 = bM + warp_m * 64 + i * 16 + g;
            const int row1 = row0 + 8;
#pragma unroll
            for (int j = 0; j < 4; j++) {
                const int col = bN + warp_n * 32 + j * 8 + 2 * t;
                if (col >= N) continue;
                const float bs0 = bias[col], bs1 = bias[col + 1];
                if (row0 < M) {
                    float2 v;
                    v.x = apply_epi(EPI, d[i][j][0] + bs0);
                    v.y = apply_epi(EPI, d[i][j][1] + bs1);
                    *(float2*)&C[(size_t)row0 * ldc + col] = v;
                }
                if (row1 < M) {
                    float2 v;
                    v.x = apply_epi(EPI, d[i][j][2] + bs0);
                    v.y = apply_epi(EPI, d[i][j][3] + bs1);
                    *(float2*)&C[(size_t)row1 * ldc + col] = v;
                }
            }
        }
    }
}

// ---------------- split-K reduce: g_dbc = sum_s part + bias ----------------
__global__ void dbc_reduce_kernel(const float* __restrict__ b_xp) {
    int idx = blockIdx.x * blockDim.x + threadIdx.x;
    if (idx >= MROWS * 64) return;
    int m = idx >> 6;
    int n = idx & 63;
    float s = b_xp[n];
#pragma unroll
    for (int z = 0; z < NSPLIT; z++)
        s += g_part[((size_t)z * MROWS + m) * 128 + n];
    g_dbc[(size_t)m * 64 + n] = s;
}

// -------- split-K reduce + transpose + seq_last for the op GEMM ------------
// out[b, hz, c] = sum_s part[s][b*CC + c][hz] + b_op[hz] + x[b, L-1, c]
__global__ void final_reduce_kernel(const float* __restrict__ x,
                                    const float* __restrict__ b_op,
                                    float* __restrict__ out) {
    int idx = blockIdx.x * blockDim.x + threadIdx.x;
    if (idx >= NB * HOR * CC) return;
    int c  = idx % CC;
    int hz = (idx / CC) % HOR;
    int b  = idx / (CC * HOR);
    int m  = b * CC + c;
    float s = b_op[hz];
#pragma unroll
    for (int z = 0; z < NSPLIT; z++)
        s += g_part[((size_t)z * MROWS + m) * 128 + hz];
    float last = x[((size_t)b * LL + (LL - 1)) * CC + c];
    out[idx] = s + last;
}

// ---------------- prep: h[b,c,l] = x[b,l,c] - x[b,L-1,c] -------------------
__global__ void prep_kernel(const float* __restrict__ x) {
    __shared__ float tile[32][33];
    int b  = blockIdx.z;
    int l0 = blockIdx.x * 32;
    int c0 = blockIdx.y * 32;
    int tx = threadIdx.x, ty = threadIdx.y;
    const float* xb = x + (size_t)b * LL * CC;
#pragma unroll
    for (int j = 0; j < 32; j += 8) {
        int l = l0 + ty + j, c = c0 + tx;
        tile[ty + j][tx] = (c < CC) ? xb[l * CC + c] : 0.f;
    }
    __syncthreads();
#pragma unroll
    for (int j = 0; j < 32; j += 8) {
        int c = c0 + ty + j, l = l0 + tx;
        if (c < CC) {
            float last = xb[(LL - 1) * CC + c];
            g_h[((size_t)b * CC + c) * DMODEL + l] = tile[tx][ty + j] - last;
        }
    }
}

// ---------------- selective scan + y, fused -------------------------------
// 8 threads per (b,d) lane, 2 states each (131K threads for latency hiding).
__global__ __launch_bounds__(256)
void scan_kernel(const float* __restrict__ A_log, const float* __restrict__ Dp) {
    const int sub = threadIdx.x & 7;                 // state group (2 states)
    const int d   = blockIdx.x * 32 + (threadIdx.x >> 3);
    const int b   = blockIdx.y;

    const float a0 = -__expf(A_log[d * DSTATE + sub * 2 + 0]);
    const float a1 = -__expf(A_log[d * DSTATE + sub * 2 + 1]);
    const float dp = Dp[d];

    float h0 = 0.f, h1 = 0.f;

    const float* xz_b  = g_xz  + (size_t)b * CC * 2 * DINNER;
    const float* dt_b  = g_dt  + (size_t)b * CC * DINNER;
    const float* dbc_b = g_dbc + (size_t)b * CC * (DTRANK + 2 * DSTATE);
    float*       yz_b  = g_yz  + (size_t)b * CC * DINNER;

    for (int t = 0; t < CC; t++) {
        const float delta = dt_b[t * DINNER + d];
        const float xv    = xz_b[t * 2 * DINNER + d];
        const float zv    = xz_b[t * 2 * DINNER + DINNER + d];
        const float2 Bm = *reinterpret_cast<const float2*>(dbc_b + t * 64 + DTRANK + sub * 2);
        const float2 Cm = *reinterpret_cast<const float2*>(dbc_b + t * 64 + DTRANK + DSTATE + sub * 2);

        const float dx = delta * xv;
        h0 = __expf(delta * a0) * h0 + dx * Bm.x;
        h1 = __expf(delta * a1) * h1 + dx * Bm.y;

        float acc = h0 * Cm.x + h1 * Cm.y;
        acc += __shfl_xor_sync(0xffffffffu, acc, 1);
        acc += __shfl_xor_sync(0xffffffffu, acc, 2);
        acc += __shfl_xor_sync(0xffffffffu, acc, 4);

        if (sub == 0) {
            yz_b[t * DINNER + d] = (acc + dp * xv) * zv;
        }
    }
}

// ---------------- launch ----------------------------------------------------
extern "C" void kernel_launch(void* const* d_in, const int* in_sizes, int n_in,
                              void* d_out, int out_size) {
    const float* x     = (const float*)d_in[0];
    const float* W_in  = (const float*)d_in[1];
    const float* b_in  = (const float*)d_in[2];
    const float* W_xp  = (const float*)d_in[3];
    const float* b_xp  = (const float*)d_in[4];
    const float* W_dt  = (const float*)d_in[5];
    const float* b_dt  = (const float*)d_in[6];
    const float* A_log = (const float*)d_in[7];
    const float* Dp    = (const float*)d_in[8];
    const float* W_out = (const float*)d_in[9];
    const float* b_out = (const float*)d_in[10];
    const float* W_op  = (const float*)d_in[11];
    const float* b_op  = (const float*)d_in[12];
    float* out = (float*)d_out;

    float *h, *xz, *dbc, *dt, *yz;
    cudaGetSymbolAddress((void**)&h,   g_h);
    cudaGetSymbolAddress((void**)&xz,  g_xz);
    cudaGetSymbolAddress((void**)&dbc, g_dbc);
    cudaGetSymbolAddress((void**)&dt,  g_dt);
    cudaGetSymbolAddress((void**)&yz,  g_yz);

    prep_kernel<<<dim3(LL / 32, (CC + 31) / 32, NB), dim3(32, 8)>>>(x);

    const int M  = MROWS;                 // 5136
    const int gM = (M + 127) / 128;       // 41

    for (int blk = 0; blk < NBLOCKS; blk++) {
        // xz = h @ W_in^T + b_in            [M, 2048], K=512   (TF32)
        mma_gemm<EPI_NONE, false><<<dim3(2 * DINNER / 128, gM), 256>>>(
            h, DMODEL, W_in, DMODEL, b_in, xz, 2 * DINNER, M, 2 * DINNER, DMODEL);

        // dbc partials: x_ @ W_xp^T         [M, 64], K=1024    (TF32 split-K 8)
        mma_gemm<EPI_NONE, true><<<dim3(1, gM, NSPLIT), 256>>>(
            xz, 2 * DINNER, W_xp, DINNER, nullptr, nullptr, 0, M, 64, DINNER);
        dbc_reduce_kernel<<<(MROWS * 64 + 255) / 256, 256>>>(b_xp);

        // dt = softplus(dbc[:, :32] @ W_dt^T + b_dt)  [M, 1024], K=32  (TF32)
        mma_gemm<EPI_SOFTPLUS, false><<<dim3(DINNER / 128, gM), 256>>>(
            dbc, 64, W_dt, DTRANK, b_dt, dt, DINNER, M, DINNER, DTRANK);

        // selective scan + y*z
        scan_kernel<<<dim3(DINNER / 32, NB), 256>>>(A_log, Dp);

        // h = gelu(yz @ W_out^T + b_out)    [M, 512], K=1024   (TF32)
        mma_gemm<EPI_GELU, false><<<dim3(DMODEL / 128, gM), 256>>>(
            yz, DINNER, W_out, DINNER, b_out, h, DMODEL, M, DMODEL, DINNER);
    }

    // op partials: h @ W_op^T               [M, 96], K=512     (TF32 split-K 8)
    mma_gemm<EPI_NONE, true><<<dim3(1, gM, NSPLIT), 256>>>(
        h, DMODEL, W_op, DMODEL, nullptr, nullptr, 0, M, HOR, DMODEL);

    // out = reduce(partials) + b_op, transposed, + seq_last
    final_reduce_kernel<<<(NB * HOR * CC + 255) / 256, 256>>>(x, b_op, out);
}